// round 1
// baseline (speedup 1.0000x reference)
#include <cuda_runtime.h>

// ---------------- problem constants ----------------
#define B_   32
#define LS_  256
#define LL_  256
#define L_   512
#define D_   2048
#define H_   16
#define DH_  128
#define T_   1000
#define TAU_ 0.07f

#define NEL  33554432   // B*L*D
#define SEL  134217728  // B*H*L*L

// ---------------- scratch (static device globals; no allocation) ----------------
__device__ float d_xt[NEL];     // x_t  [B,L,D]
__device__ float d_xT[NEL];     // x_start transposed [D,B,L]
__device__ float d_q[NEL];      // Q [B,L,D]
__device__ float d_k[NEL];      // K
__device__ float d_v[NEL];      // V
__device__ float d_o[NEL];      // attn out [B,L,D]
__device__ float d_mo[NEL];     // model_output
__device__ float d_s[SEL];      // scores [B*H, L, L]
__device__ double g_acc[4];     // 0: sum x_start^2, 1: sum (xs-mo)^2, 2: match sum, 3: ctr sum

// ---------------- helpers ----------------
__device__ __forceinline__ double blockReduceSumD(double v) {
    __shared__ double sh[8];
    #pragma unroll
    for (int o = 16; o > 0; o >>= 1) v += __shfl_down_sync(0xffffffffu, v, o);
    int lane = threadIdx.x & 31, w = threadIdx.x >> 5;
    if (lane == 0) sh[w] = v;
    __syncthreads();
    if (w == 0) {
        v = (lane < (int)(blockDim.x >> 5)) ? sh[lane] : 0.0;
        #pragma unroll
        for (int o = 4; o > 0; o >>= 1) v += __shfl_down_sync(0xffffffffu, v, o);
    }
    return v;  // valid on thread 0
}

// ---------------- kernels ----------------
__global__ void zero_acc_kernel() {
    if (threadIdx.x < 4) g_acc[threadIdx.x] = 0.0;
}

// builds x_t = sa*x_start + s1m*noise, accumulates sum(x_start^2)
__global__ __launch_bounds__(256) void prep_kernel(
    const float* __restrict__ eseq, const float* __restrict__ elab,
    const float* __restrict__ noise, const float* __restrict__ sac,
    const float* __restrict__ s1mac, const int* __restrict__ tstep)
{
    long i4 = (long)blockIdx.x * blockDim.x + threadIdx.x;  // float4 index, exact grid
    long e = i4 * 4;
    int d = (int)(e % D_);
    long bl = e / D_;
    int l = (int)(bl % L_);
    int b = (int)(bl / L_);
    float4 xs;
    if (l < LS_) xs = *(const float4*)(eseq + ((long)b * LS_ + l) * D_ + d);
    else         xs = *(const float4*)(elab + ((long)b * LL_ + (l - LS_)) * D_ + d);
    int t = tstep[b];
    float sa = sac[t], sm = s1mac[t];
    float4 nz = *(const float4*)(noise + e);
    float4 xt;
    xt.x = sa * xs.x + sm * nz.x;
    xt.y = sa * xs.y + sm * nz.y;
    xt.z = sa * xs.z + sm * nz.z;
    xt.w = sa * xs.w + sm * nz.w;
    *(float4*)(d_xt + e) = xt;
    double loc = (double)xs.x * xs.x + (double)xs.y * xs.y +
                 (double)xs.z * xs.z + (double)xs.w * xs.w;
    double bs = blockReduceSumD(loc);
    if (threadIdx.x == 0) atomicAdd(&g_acc[0], bs);
}

// x_start[b,l,d] -> xT[d,b,l]
__global__ void transpose_kernel(const float* __restrict__ eseq,
                                 const float* __restrict__ elab)
{
    __shared__ float tile[32][33];
    int b = blockIdx.z;
    int d = blockIdx.x * 32 + threadIdx.x;
    int l = blockIdx.y * 32 + threadIdx.y;
    float v;
    if (l < LS_) v = eseq[((long)b * LS_ + l) * D_ + d];
    else         v = elab[((long)b * LL_ + (l - LS_)) * D_ + d];
    tile[threadIdx.y][threadIdx.x] = v;
    __syncthreads();
    int dw = blockIdx.x * 32 + threadIdx.y;
    int lw = blockIdx.y * 32 + threadIdx.x;
    d_xT[((long)dw * B_ + b) * L_ + lw] = tile[threadIdx.x][threadIdx.y];
}

// Generic batched GEMM: C = alpha * A @ op(B).  Row-major. BM=BN=128, BK=16.
// batch z -> (zo = z/innerB, zi = z%innerB); base = zo*s1 + zi*s2 per operand.
__global__ __launch_bounds__(256) void gemm_kernel(
    const float* __restrict__ A, int lda, long sA1, long sA2,
    const float* __restrict__ Bm, int ldb, long sB1, long sB2,
    float* __restrict__ C, int ldc, long sC1, long sC2,
    int M, int N, int K, int innerB, int transB, float alpha)
{
    int z = blockIdx.z;
    int zo = z / innerB, zi = z % innerB;
    A  += zo * sA1 + zi * sA2;
    Bm += zo * sB1 + zi * sB2;
    C  += zo * sC1 + zi * sC2;
    int m0 = blockIdx.y * 128, n0 = blockIdx.x * 128;

    __shared__ float As[16][128];
    __shared__ float Bs[16][128];

    int tid = threadIdx.x;
    int tx = tid & 15, ty = tid >> 4;
    float acc[8][8];
    #pragma unroll
    for (int i = 0; i < 8; i++)
        #pragma unroll
        for (int j = 0; j < 8; j++) acc[i][j] = 0.f;

    for (int k0 = 0; k0 < K; k0 += 16) {
        #pragma unroll
        for (int it = 0; it < 2; it++) {
            int fi = it * 256 + tid;
            int r = fi >> 2, c = (fi & 3) * 4;
            float4 a = *(const float4*)(A + (long)(m0 + r) * lda + k0 + c);
            As[c + 0][r] = a.x; As[c + 1][r] = a.y;
            As[c + 2][r] = a.z; As[c + 3][r] = a.w;
        }
        if (!transB) {
            #pragma unroll
            for (int it = 0; it < 2; it++) {
                int fi = it * 256 + tid;
                int r = fi >> 5, c = (fi & 31) * 4;
                *(float4*)&Bs[r][c] = *(const float4*)(Bm + (long)(k0 + r) * ldb + n0 + c);
            }
        } else {
            #pragma unroll
            for (int it = 0; it < 2; it++) {
                int fi = it * 256 + tid;
                int r = fi >> 2, c = (fi & 3) * 4;
                float4 bb = *(const float4*)(Bm + (long)(n0 + r) * ldb + k0 + c);
                Bs[c + 0][r] = bb.x; Bs[c + 1][r] = bb.y;
                Bs[c + 2][r] = bb.z; Bs[c + 3][r] = bb.w;
            }
        }
        __syncthreads();
        #pragma unroll
        for (int kk = 0; kk < 16; kk++) {
            float a[8], bb[8];
            *(float4*)&a[0]  = *(float4*)&As[kk][ty * 8];
            *(float4*)&a[4]  = *(float4*)&As[kk][ty * 8 + 4];
            *(float4*)&bb[0] = *(float4*)&Bs[kk][tx * 8];
            *(float4*)&bb[4] = *(float4*)&Bs[kk][tx * 8 + 4];
            #pragma unroll
            for (int i = 0; i < 8; i++)
                #pragma unroll
                for (int j = 0; j < 8; j++)
                    acc[i][j] += a[i] * bb[j];
        }
        __syncthreads();
    }
    #pragma unroll
    for (int i = 0; i < 8; i++) {
        long ro = (long)(m0 + ty * 8 + i) * ldc + n0 + tx * 8;
        float4 c0 = make_float4(acc[i][0] * alpha, acc[i][1] * alpha,
                                acc[i][2] * alpha, acc[i][3] * alpha);
        float4 c1 = make_float4(acc[i][4] * alpha, acc[i][5] * alpha,
                                acc[i][6] * alpha, acc[i][7] * alpha);
        *(float4*)(C + ro) = c0;
        *(float4*)(C + ro + 4) = c1;
    }
}

// softmax over last axis of d_s, one warp per row of 512
__global__ __launch_bounds__(256) void softmax_kernel() {
    long warp = ((long)blockIdx.x * blockDim.x + threadIdx.x) >> 5;
    int lane = threadIdx.x & 31;
    float* row = d_s + warp * 512;
    float v[16];
    float m = -1e30f;
    #pragma unroll
    for (int i = 0; i < 16; i++) {
        v[i] = row[lane + i * 32];
        m = fmaxf(m, v[i]);
    }
    #pragma unroll
    for (int o = 16; o > 0; o >>= 1) m = fmaxf(m, __shfl_xor_sync(0xffffffffu, m, o));
    float s = 0.f;
    #pragma unroll
    for (int i = 0; i < 16; i++) {
        v[i] = expf(v[i] - m);
        s += v[i];
    }
    #pragma unroll
    for (int o = 16; o > 0; o >>= 1) s += __shfl_xor_sync(0xffffffffu, s, o);
    float inv = 1.0f / s;
    #pragma unroll
    for (int i = 0; i < 16; i++) row[lane + i * 32] = v[i] * inv;
}

// sum (x_start - model_output)^2
__global__ __launch_bounds__(256) void mse_kernel(
    const float* __restrict__ eseq, const float* __restrict__ elab)
{
    long i4 = (long)blockIdx.x * blockDim.x + threadIdx.x;
    long e = i4 * 4;
    int d = (int)(e % D_);
    long bl = e / D_;
    int l = (int)(bl % L_);
    int b = (int)(bl / L_);
    float4 xs;
    if (l < LS_) xs = *(const float4*)(eseq + ((long)b * LS_ + l) * D_ + d);
    else         xs = *(const float4*)(elab + ((long)b * LL_ + (l - LS_)) * D_ + d);
    float4 mo = *(const float4*)(d_mo + e);
    float dx = xs.x - mo.x, dy = xs.y - mo.y, dz = xs.z - mo.z, dw = xs.w - mo.w;
    double loc = (double)dx * dx + (double)dy * dy + (double)dz * dz + (double)dw * dw;
    double bs = blockReduceSumD(loc);
    if (threadIdx.x == 0) atomicAdd(&g_acc[1], bs);
}

// per-channel contrastive loss. grid (D, 2): mode 0 = (seq,label), mode 1 = (label,label)
__global__ __launch_bounds__(256) void contrast_kernel() {
    int d = blockIdx.x;
    int mode = blockIdx.y;
    __shared__ float f2s[32][257];
    __shared__ float f1s[8][257];
    __shared__ float inv2s[32];
    __shared__ double bsum[8];

    const float* base = d_xT + (long)d * B_ * L_;
    // f2 = label features
    #pragma unroll
    for (int it = 0; it < 32; it++) {
        int j = it, k = threadIdx.x;
        f2s[j][k] = base[(long)j * L_ + LS_ + k];
    }
    __syncthreads();
    if (threadIdx.x < 32) {
        float s = 0.f;
        #pragma unroll 8
        for (int k = 0; k < 256; k++) { float x = f2s[threadIdx.x][k]; s += x * x; }
        inv2s[threadIdx.x] = rsqrtf(s);
    }
    __syncthreads();

    int warp = threadIdx.x >> 5, lane = threadIdx.x & 31;
    double wsum = 0.0;
    for (int tile = 0; tile < 4; tile++) {
        #pragma unroll
        for (int it = 0; it < 8; it++) {
            int i = it, k = threadIdx.x;
            int bi = tile * 8 + i;
            f1s[i][k] = (mode == 0) ? base[(long)bi * L_ + k]
                                    : base[(long)bi * L_ + LS_ + k];
        }
        __syncthreads();
        // thread (warp=i_local, lane=j): sim[i][j]
        float s = 0.f;
        #pragma unroll 8
        for (int k = 0; k < 256; k++) s += f1s[warp][k] * f2s[lane][k];
        // ||f1[i]||^2 via warp-parallel partials
        float p = 0.f;
        for (int k = lane; k < 256; k += 32) { float x = f1s[warp][k]; p += x * x; }
        #pragma unroll
        for (int o = 16; o > 0; o >>= 1) p += __shfl_xor_sync(0xffffffffu, p, o);
        float invn1 = rsqrtf(p);
        float logit = s * invn1 * inv2s[lane] * (1.0f / TAU_);
        // warp logsumexp over j
        float mx = logit;
        #pragma unroll
        for (int o = 16; o > 0; o >>= 1) mx = fmaxf(mx, __shfl_xor_sync(0xffffffffu, mx, o));
        float ex = expf(logit - mx);
        float sm = ex;
        #pragma unroll
        for (int o = 16; o > 0; o >>= 1) sm += __shfl_xor_sync(0xffffffffu, sm, o);
        float lse = mx + logf(sm);
        int gi = tile * 8 + warp;
        float diag = __shfl_sync(0xffffffffu, logit, gi);
        if (lane == 0) wsum += (double)(lse - diag);
        __syncthreads();
    }
    if (lane == 0) bsum[warp] = wsum;
    __syncthreads();
    if (threadIdx.x == 0) {
        double t = 0.0;
        #pragma unroll
        for (int w = 0; w < 8; w++) t += bsum[w];
        atomicAdd(&g_acc[2 + mode], t);
    }
}

__global__ void finalize_kernel(const float* __restrict__ sac, float* __restrict__ out) {
    double inv = 1.0 / (double)NEL;
    double saT = (double)sac[T_ - 1];
    double mse = g_acc[1] * inv;
    double tT  = saT * saT * g_acc[0] * inv;
    double con = (g_acc[2] + g_acc[3]) / (2048.0 * 32.0);
    out[0] = (float)(mse + tT + con);
}

// ---------------- launch ----------------
extern "C" void kernel_launch(void* const* d_in, const int* in_sizes, int n_in,
                              void* d_out, int out_size)
{
    const float* eseq  = (const float*)d_in[0];
    const float* elab  = (const float*)d_in[1];
    const float* noise = (const float*)d_in[2];
    const float* sac   = (const float*)d_in[3];
    const float* s1m   = (const float*)d_in[4];
    const float* Wq    = (const float*)d_in[5];
    const float* Wk    = (const float*)d_in[6];
    const float* Wv    = (const float*)d_in[7];
    const float* Wo    = (const float*)d_in[8];
    const int*   ts    = (const int*)d_in[9];
    float* out = (float*)d_out;

    float *xt, *q, *k, *v, *o, *mo, *s;
    cudaGetSymbolAddress((void**)&xt, d_xt);
    cudaGetSymbolAddress((void**)&q,  d_q);
    cudaGetSymbolAddress((void**)&k,  d_k);
    cudaGetSymbolAddress((void**)&v,  d_v);
    cudaGetSymbolAddress((void**)&o,  d_o);
    cudaGetSymbolAddress((void**)&mo, d_mo);
    cudaGetSymbolAddress((void**)&s,  d_s);

    zero_acc_kernel<<<1, 32>>>();
    prep_kernel<<<32768, 256>>>(eseq, elab, noise, sac, s1m, ts);
    transpose_kernel<<<dim3(64, 16, 32), dim3(32, 32)>>>(eseq, elab);
    contrast_kernel<<<dim3(2048, 2), 256>>>();

    // Q/K/V projections: [16384,2048] = x_t @ W
    gemm_kernel<<<dim3(16, 128, 1), 256>>>(xt, 2048, 0, 0, Wq, 2048, 0, 0,
                                           q, 2048, 0, 0, 16384, 2048, 2048, 1, 0, 1.0f);
    gemm_kernel<<<dim3(16, 128, 1), 256>>>(xt, 2048, 0, 0, Wk, 2048, 0, 0,
                                           k, 2048, 0, 0, 16384, 2048, 2048, 1, 0, 1.0f);
    gemm_kernel<<<dim3(16, 128, 1), 256>>>(xt, 2048, 0, 0, Wv, 2048, 0, 0,
                                           v, 2048, 0, 0, 16384, 2048, 2048, 1, 0, 1.0f);

    // S = Q @ K^T / sqrt(dh), batched over (b,h) = 512
    gemm_kernel<<<dim3(4, 4, 512), 256>>>(q, 2048, 1048576L, 128L,
                                          k, 2048, 1048576L, 128L,
                                          s, 512, 4194304L, 262144L,
                                          512, 512, 128, 16, 1,
                                          0.08838834764831845f);
    softmax_kernel<<<32768, 256>>>();

    // O = P @ V, batched
    gemm_kernel<<<dim3(1, 4, 512), 256>>>(s, 512, 4194304L, 262144L,
                                          v, 2048, 1048576L, 128L,
                                          o, 2048, 1048576L, 128L,
                                          512, 128, 512, 16, 0, 1.0f);

    // model_output = O @ Wo
    gemm_kernel<<<dim3(16, 128, 1), 256>>>(o, 2048, 0, 0, Wo, 2048, 0, 0,
                                           mo, 2048, 0, 0, 16384, 2048, 2048, 1, 0, 1.0f);

    mse_kernel<<<32768, 256>>>(eseq, elab);
    finalize_kernel<<<1, 1>>>(sac, out);
}

// round 3
// speedup vs baseline: 4.6570x; 4.6570x over previous
#include <cuda_runtime.h>
#include <cuda_bf16.h>
#include <cstdint>

// ---------------- problem constants ----------------
#define B_   32
#define LS_  256
#define LL_  256
#define L_   512
#define D_   2048
#define H_   16
#define DH_  128
#define T_   1000
#define TAU_ 0.07f

#define NEL  33554432L   // B*L*D
#define SEL  134217728L  // B*H*L*L

// ---------------- scratch buffers (static, no allocation) ----------------
__device__ __nv_bfloat16 d_xtb[NEL];            // x_t bf16 [B,L,D]
__device__ __nv_bfloat16 d_wt[4L*2048*2048];    // WqT,WkT,WvT,WoT bf16 [N,K]
__device__ __nv_bfloat16 d_qb[NEL];             // Q bf16
__device__ __nv_bfloat16 d_kb[NEL];             // K bf16
__device__ __nv_bfloat16 d_vb[NEL];             // V bf16
__device__ __nv_bfloat16 d_vt[NEL];             // V^T per head [z=512][128][512]
__device__ __nv_bfloat16 d_ob[NEL];             // attn out bf16
__device__ __nv_bfloat16 d_sb[SEL];             // scores/probs bf16 [512][512][512]
__device__ float d_mo[NEL];                     // model_output fp32
__device__ float d_xT[NEL];                     // x_start^T [D,B,L] fp32
__device__ double g_acc[4];

// ---------------- mma helpers ----------------
__device__ __forceinline__ void mma16816(float* c, const uint32_t* a, const uint32_t* b) {
    asm volatile(
        "mma.sync.aligned.m16n8k16.row.col.f32.bf16.bf16.f32 "
        "{%0,%1,%2,%3}, {%4,%5,%6,%7}, {%8,%9}, {%0,%1,%2,%3};"
        : "+f"(c[0]), "+f"(c[1]), "+f"(c[2]), "+f"(c[3])
        : "r"(a[0]), "r"(a[1]), "r"(a[2]), "r"(a[3]), "r"(b[0]), "r"(b[1]));
}
__device__ __forceinline__ void ldsm4(uint32_t* f, uint32_t addr) {
    asm volatile("ldmatrix.sync.aligned.m8n8.x4.shared.b16 {%0,%1,%2,%3}, [%4];"
                 : "=r"(f[0]), "=r"(f[1]), "=r"(f[2]), "=r"(f[3]) : "r"(addr));
}

// ---------------- batched bf16 MMA GEMM: C = alpha * A[M,K] @ B[N,K]^T ----------------
// CTA tile 128x128, BK=32, cp.async double-buffered, 8 warps of 32x64.
// smem rows padded to 80B (64B data + 16B) -> conflict-free ldmatrix & stores.
#define SROW 80
#define SBUF 10240   // 128*80

__global__ __launch_bounds__(256) void mma_gemm(
    const __nv_bfloat16* __restrict__ A, int lda, long sA1, long sA2,
    const __nv_bfloat16* __restrict__ Bm, int ldb, long sB1, long sB2,
    void* __restrict__ Cv, int ldc, long sC1, long sC2,
    int K, int innerB, float alpha, int outBf16)
{
    __shared__ __align__(16) char sAm[2 * SBUF];
    __shared__ __align__(16) char sBm[2 * SBUF];

    int tid = threadIdx.x, lane = tid & 31, wid = tid >> 5;
    int z = blockIdx.z, zo = z / innerB, zi = z - zo * innerB;
    A  += zo * sA1 + zi * sA2;
    Bm += zo * sB1 + zi * sB2;
    long cb = zo * sC1 + zi * sC2;
    int m0 = blockIdx.y << 7, n0 = blockIdx.x << 7;
    int wm = wid & 3, wn = wid >> 2;

    uint32_t saA = (uint32_t)__cvta_generic_to_shared(sAm);
    uint32_t saB = (uint32_t)__cvta_generic_to_shared(sBm);
    const __nv_bfloat16* Ag = A + (long)m0 * lda;
    const __nv_bfloat16* Bg = Bm + (long)n0 * ldb;

    float acc[2][8][4];
    #pragma unroll
    for (int i = 0; i < 2; i++)
        #pragma unroll
        for (int j = 0; j < 8; j++)
            #pragma unroll
            for (int q = 0; q < 4; q++) acc[i][j][q] = 0.f;

#define LOAD_TILE(sidx, buf) do {                                               \
    const __nv_bfloat16* Ab_ = Ag + (long)(sidx) * 32;                          \
    const __nv_bfloat16* Bb_ = Bg + (long)(sidx) * 32;                          \
    _Pragma("unroll")                                                           \
    for (int it_ = 0; it_ < 2; it_++) {                                         \
        int ch_ = it_ * 256 + tid;                                              \
        int r_ = ch_ >> 2, c_ = ch_ & 3;                                        \
        uint32_t so_ = (uint32_t)((buf) * SBUF + r_ * SROW + c_ * 16);          \
        const void* ga_ = Ab_ + (long)r_ * lda + c_ * 8;                        \
        asm volatile("cp.async.cg.shared.global [%0], [%1], 16;"                \
                     :: "r"(saA + so_), "l"(ga_));                              \
        const void* gb_ = Bb_ + (long)r_ * ldb + c_ * 8;                        \
        asm volatile("cp.async.cg.shared.global [%0], [%1], 16;"                \
                     :: "r"(saB + so_), "l"(gb_));                              \
    }                                                                           \
} while (0)

    int nt = K >> 5;
    LOAD_TILE(0, 0);
    asm volatile("cp.async.commit_group;" ::: "memory");

    for (int s = 0; s < nt; s++) {
        if (s + 1 < nt) {
            LOAD_TILE(s + 1, (s + 1) & 1);
            asm volatile("cp.async.commit_group;" ::: "memory");
            asm volatile("cp.async.wait_group 1;" ::: "memory");
        } else {
            asm volatile("cp.async.wait_group 0;" ::: "memory");
        }
        __syncthreads();

        int b = s & 1;
        uint32_t baseA = saA + b * SBUF;
        uint32_t baseB = saB + b * SBUF;
        #pragma unroll
        for (int kk = 0; kk < 2; kk++) {
            uint32_t af[2][4];
            #pragma unroll
            for (int mi = 0; mi < 2; mi++) {
                int row = (wm << 5) + (mi << 4) + (lane & 15);
                uint32_t ad = baseA + (uint32_t)(row * SROW + (kk << 5) + ((lane >> 4) << 4));
                ldsm4(af[mi], ad);
            }
            uint32_t bf[4][4];
            #pragma unroll
            for (int g = 0; g < 4; g++) {
                int nrow = (wn << 6) + (g << 4) + ((lane >> 4) << 3) + (lane & 7);
                uint32_t bd = baseB + (uint32_t)(nrow * SROW + (kk << 5) + (((lane >> 3) & 1) << 4));
                ldsm4(bf[g], bd);
            }
            #pragma unroll
            for (int mi = 0; mi < 2; mi++)
                #pragma unroll
                for (int ni = 0; ni < 8; ni++)
                    mma16816(acc[mi][ni], af[mi], &bf[ni >> 1][(ni & 1) * 2]);
        }
        __syncthreads();
    }

    // epilogue
    int tg = lane >> 2, tc = lane & 3;
    #pragma unroll
    for (int mi = 0; mi < 2; mi++) {
        #pragma unroll
        for (int ni = 0; ni < 8; ni++) {
            int row = m0 + (wm << 5) + (mi << 4) + tg;
            int col = n0 + (wn << 6) + (ni << 3) + tc * 2;
            float* a4 = acc[mi][ni];
            if (outBf16) {
                __nv_bfloat16* C = (__nv_bfloat16*)Cv;
                __nv_bfloat162 p0 = __floats2bfloat162_rn(a4[0] * alpha, a4[1] * alpha);
                __nv_bfloat162 p1 = __floats2bfloat162_rn(a4[2] * alpha, a4[3] * alpha);
                *(__nv_bfloat162*)(C + cb + (long)row * ldc + col) = p0;
                *(__nv_bfloat162*)(C + cb + (long)(row + 8) * ldc + col) = p1;
            } else {
                float* C = (float*)Cv;
                *(float2*)(C + cb + (long)row * ldc + col) =
                    make_float2(a4[0] * alpha, a4[1] * alpha);
                *(float2*)(C + cb + (long)(row + 8) * ldc + col) =
                    make_float2(a4[2] * alpha, a4[3] * alpha);
            }
        }
    }
}

// ---------------- reduction helper ----------------
__device__ __forceinline__ double blockReduceSumD(double v) {
    __shared__ double sh[8];
    #pragma unroll
    for (int o = 16; o > 0; o >>= 1) v += __shfl_down_sync(0xffffffffu, v, o);
    int lane = threadIdx.x & 31, w = threadIdx.x >> 5;
    if (lane == 0) sh[w] = v;
    __syncthreads();
    if (w == 0) {
        v = (lane < (int)(blockDim.x >> 5)) ? sh[lane] : 0.0;
        #pragma unroll
        for (int o = 4; o > 0; o >>= 1) v += __shfl_down_sync(0xffffffffu, v, o);
    }
    return v;
}

__global__ void zero_acc_kernel() {
    if (threadIdx.x < 4) g_acc[threadIdx.x] = 0.0;
}

// x_t = sa*x_start + s1m*noise -> bf16; accumulate sum(x_start^2)
__global__ __launch_bounds__(256) void prep_kernel(
    const float* __restrict__ eseq, const float* __restrict__ elab,
    const float* __restrict__ noise, const float* __restrict__ sac,
    const float* __restrict__ s1mac, const int* __restrict__ tstep)
{
    long i4 = (long)blockIdx.x * blockDim.x + threadIdx.x;
    long e = i4 * 4;
    int d = (int)(e % D_);
    long bl = e / D_;
    int l = (int)(bl % L_);
    int b = (int)(bl / L_);
    float4 xs;
    if (l < LS_) xs = *(const float4*)(eseq + ((long)b * LS_ + l) * D_ + d);
    else         xs = *(const float4*)(elab + ((long)b * LL_ + (l - LS_)) * D_ + d);
    int t = tstep[b];
    float sa = sac[t], sm = s1mac[t];
    float4 nz = *(const float4*)(noise + e);
    __nv_bfloat162* ob = (__nv_bfloat162*)(d_xtb + e);
    ob[0] = __floats2bfloat162_rn(sa * xs.x + sm * nz.x, sa * xs.y + sm * nz.y);
    ob[1] = __floats2bfloat162_rn(sa * xs.z + sm * nz.z, sa * xs.w + sm * nz.w);
    double loc = (double)xs.x * xs.x + (double)xs.y * xs.y +
                 (double)xs.z * xs.z + (double)xs.w * xs.w;
    double bs = blockReduceSumD(loc);
    if (threadIdx.x == 0) atomicAdd(&g_acc[0], bs);
}

// x_start[b,l,d] -> xT[d,b,l] (fp32, for contrast)
__global__ void transpose_kernel(const float* __restrict__ eseq,
                                 const float* __restrict__ elab)
{
    __shared__ float tile[32][33];
    int b = blockIdx.z;
    int d = blockIdx.x * 32 + threadIdx.x;
    int l = blockIdx.y * 32 + threadIdx.y;
    float v;
    if (l < LS_) v = eseq[((long)b * LS_ + l) * D_ + d];
    else         v = elab[((long)b * LL_ + (l - LS_)) * D_ + d];
    tile[threadIdx.y][threadIdx.x] = v;
    __syncthreads();
    int dw = blockIdx.x * 32 + threadIdx.y;
    int lw = blockIdx.y * 32 + threadIdx.x;
    d_xT[((long)dw * B_ + b) * L_ + lw] = tile[threadIdx.x][threadIdx.y];
}

// W[k,n] -> WT[n,k] bf16, 4 weights by blockIdx.z
__global__ void wt_kernel(const float* __restrict__ W0, const float* __restrict__ W1,
                          const float* __restrict__ W2, const float* __restrict__ W3)
{
    __shared__ float t[32][33];
    int zz = blockIdx.z;
    const float* W = (zz == 0) ? W0 : (zz == 1) ? W1 : (zz == 2) ? W2 : W3;
    int n = blockIdx.x * 32 + threadIdx.x;
    int k = blockIdx.y * 32 + threadIdx.y;
    t[threadIdx.y][threadIdx.x] = W[(long)k * 2048 + n];
    __syncthreads();
    int nn = blockIdx.x * 32 + threadIdx.y;
    int kk = blockIdx.y * 32 + threadIdx.x;
    d_wt[(long)zz * 4194304 + (long)nn * 2048 + kk] = __float2bfloat16(t[threadIdx.x][threadIdx.y]);
}

// V[b,l,h*128+dh] -> VT[z=b*16+h][dh][l] bf16
__global__ void vt_kernel() {
    __shared__ __nv_bfloat16 t[32][33];
    int z = blockIdx.z;
    int b = z >> 4, h = z & 15;
    int dh = blockIdx.x * 32 + threadIdx.x;
    int l  = blockIdx.y * 32 + threadIdx.y;
    t[threadIdx.y][threadIdx.x] = d_vb[((long)b * 512 + l) * 2048 + h * 128 + dh];
    __syncthreads();
    int dho = blockIdx.x * 32 + threadIdx.y;
    int lo  = blockIdx.y * 32 + threadIdx.x;
    d_vt[(long)z * 65536 + (long)dho * 512 + lo] = t[threadIdx.x][threadIdx.y];
}

// softmax over rows of 512 bf16, in place; one warp per row
__global__ __launch_bounds__(256) void softmax_bf16() {
    long warp = ((long)blockIdx.x * blockDim.x + threadIdx.x) >> 5;
    int lane = threadIdx.x & 31;
    __nv_bfloat162* row = ((__nv_bfloat162*)d_sb) + warp * 256;
    float v[16];
    float m = -1e30f;
    #pragma unroll
    for (int i = 0; i < 8; i++) {
        __nv_bfloat162 p = row[lane + i * 32];
        v[2 * i]     = __bfloat162float(p.x);
        v[2 * i + 1] = __bfloat162float(p.y);
        m = fmaxf(m, fmaxf(v[2 * i], v[2 * i + 1]));
    }
    #pragma unroll
    for (int o = 16; o > 0; o >>= 1) m = fmaxf(m, __shfl_xor_sync(0xffffffffu, m, o));
    float s = 0.f;
    #pragma unroll
    for (int i = 0; i < 16; i++) { v[i] = expf(v[i] - m); s += v[i]; }
    #pragma unroll
    for (int o = 16; o > 0; o >>= 1) s += __shfl_xor_sync(0xffffffffu, s, o);
    float inv = 1.0f / s;
    #pragma unroll
    for (int i = 0; i < 8; i++)
        row[lane + i * 32] = __floats2bfloat162_rn(v[2 * i] * inv, v[2 * i + 1] * inv);
}

// sum (x_start - model_output)^2
__global__ __launch_bounds__(256) void mse_kernel(
    const float* __restrict__ eseq, const float* __restrict__ elab)
{
    long i4 = (long)blockIdx.x * blockDim.x + threadIdx.x;
    long e = i4 * 4;
    int d = (int)(e % D_);
    long bl = e / D_;
    int l = (int)(bl % L_);
    int b = (int)(bl / L_);
    float4 xs;
    if (l < LS_) xs = *(const float4*)(eseq + ((long)b * LS_ + l) * D_ + d);
    else         xs = *(const float4*)(elab + ((long)b * LL_ + (l - LS_)) * D_ + d);
    float4 mo = *(const float4*)(d_mo + e);
    float dx = xs.x - mo.x, dy = xs.y - mo.y, dz = xs.z - mo.z, dw = xs.w - mo.w;
    double loc = (double)dx * dx + (double)dy * dy + (double)dz * dz + (double)dw * dw;
    double bs = blockReduceSumD(loc);
    if (threadIdx.x == 0) atomicAdd(&g_acc[1], bs);
}

// per-channel contrastive loss. grid (D, 2): mode 0 = (seq,label), mode 1 = (label,label)
__global__ __launch_bounds__(256) void contrast_kernel() {
    int d = blockIdx.x;
    int mode = blockIdx.y;
    __shared__ float f2s[32][257];
    __shared__ float f1s[8][257];
    __shared__ float inv2s[32];
    __shared__ double bsum[8];

    const float* base = d_xT + (long)d * B_ * L_;
    #pragma unroll
    for (int it = 0; it < 32; it++) {
        f2s[it][threadIdx.x] = base[(long)it * L_ + LS_ + threadIdx.x];
    }
    __syncthreads();
    if (threadIdx.x < 32) {
        float s = 0.f;
        #pragma unroll 8
        for (int k = 0; k < 256; k++) { float x = f2s[threadIdx.x][k]; s += x * x; }
        inv2s[threadIdx.x] = rsqrtf(s);
    }
    __syncthreads();

    int warp = threadIdx.x >> 5, lane = threadIdx.x & 31;
    double wsum = 0.0;
    for (int tile = 0; tile < 4; tile++) {
        #pragma unroll
        for (int it = 0; it < 8; it++) {
            int bi = tile * 8 + it;
            f1s[it][threadIdx.x] = (mode == 0) ? base[(long)bi * L_ + threadIdx.x]
                                               : base[(long)bi * L_ + LS_ + threadIdx.x];
        }
        __syncthreads();
        float s = 0.f;
        #pragma unroll 8
        for (int k = 0; k < 256; k++) s += f1s[warp][k] * f2s[lane][k];
        float p = 0.f;
        for (int k = lane; k < 256; k += 32) { float x = f1s[warp][k]; p += x * x; }
        #pragma unroll
        for (int o = 16; o > 0; o >>= 1) p += __shfl_xor_sync(0xffffffffu, p, o);
        float invn1 = rsqrtf(p);
        float logit = s * invn1 * inv2s[lane] * (1.0f / TAU_);
        float mx = logit;
        #pragma unroll
        for (int o = 16; o > 0; o >>= 1) mx = fmaxf(mx, __shfl_xor_sync(0xffffffffu, mx, o));
        float ex = expf(logit - mx);
        float sm = ex;
        #pragma unroll
        for (int o = 16; o > 0; o >>= 1) sm += __shfl_xor_sync(0xffffffffu, sm, o);
        float lse = mx + logf(sm);
        int gi = tile * 8 + warp;
        float diag = __shfl_sync(0xffffffffu, logit, gi);
        if (lane == 0) wsum += (double)(lse - diag);
        __syncthreads();
    }
    if (lane == 0) bsum[warp] = wsum;
    __syncthreads();
    if (threadIdx.x == 0) {
        double t = 0.0;
        #pragma unroll
        for (int w = 0; w < 8; w++) t += bsum[w];
        atomicAdd(&g_acc[2 + mode], t);
    }
}

__global__ void finalize_kernel(const float* __restrict__ sac, float* __restrict__ out) {
    double inv = 1.0 / (double)NEL;
    double saT = (double)sac[T_ - 1];
    double mse = g_acc[1] * inv;
    double tT  = saT * saT * g_acc[0] * inv;
    double con = (g_acc[2] + g_acc[3]) / (2048.0 * 32.0);
    out[0] = (float)(mse + tT + con);
}

// ---------------- launch ----------------
extern "C" void kernel_launch(void* const* d_in, const int* in_sizes, int n_in,
                              void* d_out, int out_size)
{
    const float* eseq  = (const float*)d_in[0];
    const float* elab  = (const float*)d_in[1];
    const float* noise = (const float*)d_in[2];
    const float* sac   = (const float*)d_in[3];
    const float* s1m   = (const float*)d_in[4];
    const float* Wq    = (const float*)d_in[5];
    const float* Wk    = (const float*)d_in[6];
    const float* Wv    = (const float*)d_in[7];
    const float* Wo    = (const float*)d_in[8];
    const int*   ts    = (const int*)d_in[9];
    float* out = (float*)d_out;

    __nv_bfloat16 *xtb, *wt, *qb, *kb, *vb, *vt, *ob, *sb;
    float *mo;
    cudaGetSymbolAddress((void**)&xtb, d_xtb);
    cudaGetSymbolAddress((void**)&wt,  d_wt);
    cudaGetSymbolAddress((void**)&qb,  d_qb);
    cudaGetSymbolAddress((void**)&kb,  d_kb);
    cudaGetSymbolAddress((void**)&vb,  d_vb);
    cudaGetSymbolAddress((void**)&vt,  d_vt);
    cudaGetSymbolAddress((void**)&ob,  d_ob);
    cudaGetSymbolAddress((void**)&sb,  d_sb);
    cudaGetSymbolAddress((void**)&mo,  d_mo);

    zero_acc_kernel<<<1, 32>>>();
    prep_kernel<<<32768, 256>>>(eseq, elab, noise, sac, s1m, ts);
    transpose_kernel<<<dim3(64, 16, 32), dim3(32, 32)>>>(eseq, elab);
    contrast_kernel<<<dim3(2048, 2), 256>>>();
    wt_kernel<<<dim3(64, 64, 4), dim3(32, 32)>>>(Wq, Wk, Wv, Wo);

    // Q/K/V projections: [16384,2048] = x_t @ W^T, bf16 out
    mma_gemm<<<dim3(16, 128, 1), 256>>>(
        xtb, 2048, 0, 0, wt + 0L * 4194304, 2048, 0, 0,
        qb, 2048, 0, 0, 2048, 1, 1.0f, 1);
    mma_gemm<<<dim3(16, 128, 1), 256>>>(
        xtb, 2048, 0, 0, wt + 1L * 4194304, 2048, 0, 0,
        kb, 2048, 0, 0, 2048, 1, 1.0f, 1);
    mma_gemm<<<dim3(16, 128, 1), 256>>>(
        xtb, 2048, 0, 0, wt + 2L * 4194304, 2048, 0, 0,
        vb, 2048, 0, 0, 2048, 1, 1.0f, 1);

    vt_kernel<<<dim3(4, 16, 512), dim3(32, 32)>>>();

    // S = Q @ K^T / sqrt(dh): per head M=N=512, K=128
    mma_gemm<<<dim3(4, 4, 512), 256>>>(
        qb, 2048, 1048576L, 128L,
        kb, 2048, 1048576L, 128L,
        sb, 512, 4194304L, 262144L,
        128, 16, 0.08838834764831845f, 1);

    softmax_bf16<<<32768, 256>>>();

    // O = P @ V: per head M=512, N=128, K=512  (B = V^T, rows = dh)
    mma_gemm<<<dim3(1, 4, 512), 256>>>(
        sb, 512, 4194304L, 262144L,
        vt, 512, 1048576L, 65536L,
        ob, 2048, 1048576L, 128L,
        512, 16, 1.0f, 1);

    // model_output = O @ Wo^T: fp32 out
    mma_gemm<<<dim3(16, 128, 1), 256>>>(
        ob, 2048, 0, 0, wt + 3L * 4194304, 2048, 0, 0,
        mo, 2048, 0, 0, 2048, 1, 1.0f, 0);

    mse_kernel<<<32768, 256>>>(eseq, elab);
    finalize_kernel<<<1, 1>>>(sac, out);
}